// round 2
// baseline (speedup 1.0000x reference)
#include <cuda_runtime.h>
#include <math.h>
#include <stdint.h>
#include <stddef.h>

// ---------------- problem constants ----------------
#define B_    2048
#define T_    512
#define DIN_  32
#define DH_   96
#define G4_   384        // 4*DH
#define KIN_  128        // DIN + DH
#define RPB_  14         // batch rows per LSTM block
#define NB1_  147        // ceil(2048/14)
#define NT1_  384        // LSTM threads/block
#define NT2_  128        // attention threads/block
#define PITCH 20         // floats per k-row of input staging (80 B, 16B-aligned)

// ---------------- device scratch (no runtime alloc allowed) ----------------
__device__ float g_H [(size_t)B_ * T_ * DH_];   // hidden states (only t < len written)
__device__ float g_hT[(size_t)B_ * DH_];        // final hidden state

// ---------------- smem layout (bytes) for LSTM kernel ----------------
#define OFF_W     0
#define SZ_W      (KIN_ * G4_ * 4)              // 196608
#define OFF_INP   (OFF_W + SZ_W)
#define SZ_INP    (KIN_ * PITCH * 4)            // 10240
#define OFF_G2    (OFF_INP + SZ_INP)
#define SZ_G2     (7 * G4_ * 8)                 // 21504 (float2 per (rowpair, gatecol))
#define OFF_BIAS  (OFF_G2 + SZ_G2)
#define SZ_BIAS   (G4_ * 4)                     // 1536
#define OFF_LEN   (OFF_BIAS + SZ_BIAS)
#define SZ_LEN    (16 * 4)
#define SMEM1     (OFF_LEN + SZ_LEN)            // 229,952 B  (<= 227 KB limit)

// packed f32x2 FMA (sm_103a; only reachable via PTX)
#define FMA2(acc, in, wv) \
  asm("fma.rn.f32x2 %0, %1, %2, %0;" : "+l"(acc) : "l"(in), "l"(wv))

__device__ __forceinline__ float sigf(float xv) {
  return __fdividef(1.f, 1.f + __expf(-xv));
}
__device__ __forceinline__ float tanh_acc(float xv) {
  float e = __expf(2.f * xv);            // inf-safe: +inf -> 1, 0 -> -1
  return 1.f - __fdividef(2.f, e + 1.f);
}

// one (row-pair, dim) activation update
__device__ __forceinline__ void lstm_act(
    const float2* __restrict__ G2, int rp, int d, int t,
    float bi, float bf, float bgg, float bo,
    int L0, int L1, float& cx, float& cy,
    float* hslot, float* H0, float* H1)
{
  float2 gI = G2[rp*G4_ + d];
  float2 gF = G2[rp*G4_ + 96  + d];
  float2 gG = G2[rp*G4_ + 192 + d];
  float2 gO = G2[rp*G4_ + 288 + d];
  float2 hold = *(float2*)hslot;

  // row A (.x)
  {
    float ii = sigf(gI.x + bi);
    float ff = sigf(gF.x + bf);
    float tg = tanh_acc(gG.x + bgg);
    float oo = sigf(gO.x + bo);
    float cn = ff * cx + ii * tg;
    float hn = oo * tanh_acc(cn);
    bool  m  = (t < L0);
    cx = m ? cn : cx;
    hold.x = m ? hn : hold.x;
    if (m) H0[(size_t)t * DH_] = hn;
  }
  // row B (.y)
  {
    float ii = sigf(gI.y + bi);
    float ff = sigf(gF.y + bf);
    float tg = tanh_acc(gG.y + bgg);
    float oo = sigf(gO.y + bo);
    float cn = ff * cy + ii * tg;
    float hn = oo * tanh_acc(cn);
    bool  m  = (t < L1);
    cy = m ? cn : cy;
    hold.y = m ? hn : hold.y;
    if (m) H1[(size_t)t * DH_] = hn;
  }
  *(float2*)hslot = hold;
}

// =====================================================================
// Kernel 1: fused LSTM over all timesteps. One block = 14 batch rows.
// =====================================================================
__global__ void __launch_bounds__(NT1_, 1)
lstm_kernel(const float* __restrict__ x, const int* __restrict__ lengths,
            const float* __restrict__ Wih, const float* __restrict__ Whh,
            const float* __restrict__ bih, const float* __restrict__ bhh)
{
  extern __shared__ char smem[];
  float* Wsm  = (float*)(smem + OFF_W);     // [k=128][j=384]
  float* inp  = (float*)(smem + OFF_INP);   // [k=128][PITCH]; scalar (k,r) at k*PITCH+r
  float* g2f  = (float*)(smem + OFF_G2);    // float2 [rp=7][j=384]
  float* bias = (float*)(smem + OFF_BIAS);  // [384]
  int*   lenm = (int*)(smem + OFF_LEN);     // [14] + maxlen at [15]

  const int tid = threadIdx.x;
  const int b0  = blockIdx.x * RPB_;

  // ---- load combined weights (transposed: k-major) ----
  for (int idx = tid; idx < G4_ * KIN_; idx += NT1_) {
    int j = idx >> 7, k = idx & 127;
    float v = (k < DIN_) ? Wih[j * DIN_ + k] : Whh[j * DH_ + (k - DIN_)];
    Wsm[k * G4_ + j] = v;
  }
  for (int j = tid; j < G4_; j += NT1_) bias[j] = bih[j] + bhh[j];
  for (int i = tid; i < KIN_ * PITCH; i += NT1_) inp[i] = 0.f;
  if (tid < 16) {
    int L = 0;
    if (tid < RPB_ && (b0 + tid) < B_) L = lengths[b0 + tid];
    lenm[tid] = L;
  }
  __syncthreads();
  if (tid == 0) {
    int m = 0;
    #pragma unroll
    for (int r = 0; r < RPB_; ++r) m = max(m, lenm[r]);
    lenm[15] = m;
  }
  // stage x(t=0)
  for (int idx = tid; idx < RPB_ * DIN_; idx += NT1_) {
    int r = idx >> 5, k = idx & 31;
    if (b0 + r < B_)
      inp[k * PITCH + r] = x[(size_t)(b0 + r) * T_ * DIN_ + k];
  }
  __syncthreads();
  const int maxlen = lenm[15];

  // ---- per-thread static element assignments ----
  // activation pair-elements: e0 = tid (always), e1 = tid+384 (tid<288)
  const int e0  = tid;
  const int rp0 = e0 / 96, d0 = e0 % 96;
  const bool has1 = (tid < 7 * 96 - NT1_);   // tid < 288
  const int e1  = tid + NT1_;
  const int rp1 = has1 ? (e1 / 96) : 0;
  const int d1  = has1 ? (e1 % 96) : 0;

  float bi0 = bias[d0], bf0 = bias[96 + d0], bg0 = bias[192 + d0], bo0 = bias[288 + d0];
  float bi1 = bias[d1], bf1 = bias[96 + d1], bg1 = bias[192 + d1], bo1 = bias[288 + d1];
  const int L00 = lenm[2 * rp0], L01 = lenm[2 * rp0 + 1];
  const int L10 = lenm[2 * rp1], L11 = lenm[2 * rp1 + 1];
  float cx0 = 0.f, cy0 = 0.f, cx1 = 0.f, cy1 = 0.f;
  float* hs0 = &inp[(32 + d0) * PITCH + 2 * rp0];
  float* hs1 = &inp[(32 + d1) * PITCH + 2 * rp1];
  const int r00 = min(b0 + 2 * rp0,     B_ - 1);
  const int r01 = min(b0 + 2 * rp0 + 1, B_ - 1);
  const int r10 = min(b0 + 2 * rp1,     B_ - 1);
  const int r11 = min(b0 + 2 * rp1 + 1, B_ - 1);
  float* H00 = &g_H[(size_t)r00 * T_ * DH_ + d0];
  float* H01 = &g_H[(size_t)r01 * T_ * DH_ + d0];
  float* H10 = &g_H[(size_t)r10 * T_ * DH_ + d1];
  float* H11 = &g_H[(size_t)r11 * T_ * DH_ + d1];

  // x prefetch assignments (448 scalars: idx = tid, tid+384)
  const int xr0 = tid >> 5, xk0 = tid & 31;
  const float* xp0 = (b0 + xr0 < B_) ? &x[(size_t)(b0 + xr0) * T_ * DIN_ + xk0] : 0;
  const int xs0 = xk0 * PITCH + xr0;
  const int xi1 = tid + NT1_;
  const bool hasx1 = (xi1 < RPB_ * DIN_);
  const int xr1 = xi1 >> 5, xk1 = xi1 & 31;
  const float* xp1 = (hasx1 && (b0 + xr1) < B_) ? &x[(size_t)(b0 + xr1) * T_ * DIN_ + xk1] : 0;
  const int xs1 = hasx1 ? (xk1 * PITCH + xr1) : xs0;

  const float2* G2 = (const float2*)g2f;
  unsigned long long* g2u = (unsigned long long*)g2f;

  for (int t = 0; t < maxlen; ++t) {
    // ------------- GEMM: g[r][j] = sum_k in[r][k] * W[j][k] -------------
    unsigned long long a0 = 0, a1 = 0, a2 = 0, a3 = 0, a4 = 0, a5 = 0, a6 = 0;
    const float* Wc = Wsm + tid;
    #pragma unroll 16
    for (int k = 0; k < KIN_; ++k) {
      float w = Wc[k * G4_];
      unsigned long long wv;
      asm("mov.b64 %0, {%1,%1};" : "=l"(wv) : "f"(w));
      const float* row = inp + k * PITCH;
      ulonglong2 p0 = *(const ulonglong2*)(row);
      ulonglong2 p1 = *(const ulonglong2*)(row + 4);
      ulonglong2 p2 = *(const ulonglong2*)(row + 8);
      unsigned long long p6 = *(const unsigned long long*)(row + 12);
      FMA2(a0, p0.x, wv); FMA2(a1, p0.y, wv);
      FMA2(a2, p1.x, wv); FMA2(a3, p1.y, wv);
      FMA2(a4, p2.x, wv); FMA2(a5, p2.y, wv);
      FMA2(a6, p6,   wv);
    }
    g2u[0 * G4_ + tid] = a0;
    g2u[1 * G4_ + tid] = a1;
    g2u[2 * G4_ + tid] = a2;
    g2u[3 * G4_ + tid] = a3;
    g2u[4 * G4_ + tid] = a4;
    g2u[5 * G4_ + tid] = a5;
    g2u[6 * G4_ + tid] = a6;

    // prefetch x(t+1) into registers (overlaps with barrier + activation)
    float xv0 = 0.f, xv1 = 0.f;
    if (t + 1 < T_) {
      if (xp0) xv0 = __ldg(xp0 + (size_t)(t + 1) * DIN_);
      if (xp1) xv1 = __ldg(xp1 + (size_t)(t + 1) * DIN_);
    }
    __syncthreads();

    // ------------- activations + state update -------------
    lstm_act(G2, rp0, d0, t, bi0, bf0, bg0, bo0, L00, L01, cx0, cy0, hs0, H00, H01);
    if (has1)
      lstm_act(G2, rp1, d1, t, bi1, bf1, bg1, bo1, L10, L11, cx1, cy1, hs1, H10, H11);

    // stage x(t+1)
    inp[xs0] = xv0;
    if (hasx1) inp[xs1] = xv1;
    __syncthreads();
  }

  // ---- write final hidden state ----
  for (int idx = tid; idx < RPB_ * DH_; idx += NT1_) {
    int r = idx / DH_, d = idx % DH_;
    if (b0 + r < B_)
      g_hT[(size_t)(b0 + r) * DH_ + d] = inp[(32 + d) * PITCH + r];
  }
}

// =====================================================================
// Kernel 2: attention (K/V folded into weight space) + top-2 MoE.
// One block per batch row.
// =====================================================================
__global__ void __launch_bounds__(NT2_)
attn_moe_kernel(const int* __restrict__ lengths,
                const float* __restrict__ Wq, const float* __restrict__ bq,
                const float* __restrict__ Wk, const float* __restrict__ bk,
                const float* __restrict__ Wv, const float* __restrict__ bv,
                const float* __restrict__ Wg, const float* __restrict__ bg,
                const float* __restrict__ We1, const float* __restrict__ be1,
                const float* __restrict__ We2, const float* __restrict__ be2,
                float* __restrict__ out)
{
  __shared__ float alpha[T_];
  __shared__ float hTs[DH_], Qs[DH_], us[DH_], ss[DH_], feats[2 * DH_];
  __shared__ float red[256];
  __shared__ float sc[5];
  __shared__ int   isc[2];

  const int b = blockIdx.x;
  const int tid = threadIdx.x;
  const float rs = 0.10206207261596575f;   // 1/sqrt(96)

  if (tid < DH_) hTs[tid] = g_hT[(size_t)b * DH_ + tid];
  __syncthreads();

  if (tid < DH_) {
    float a = bq[tid];
    const float* wr = Wq + tid * DH_;
    #pragma unroll 8
    for (int k = 0; k < DH_; ++k) a += hTs[k] * wr[k];
    Qs[tid] = a;
  }
  __syncthreads();

  if (tid < DH_) {
    float a = 0.f;
    #pragma unroll 8
    for (int j = 0; j < DH_; ++j) a += Qs[j] * Wk[j * DH_ + tid];
    us[tid] = a * rs;
  }
  if (tid == NT2_ - 1) {
    float a = 0.f;
    for (int j = 0; j < DH_; ++j) a += Qs[j] * bk[j];
    sc[0] = a * rs;
  }
  __syncthreads();

  const int len = lengths[b];
  const float qbk = sc[0];

  // ---- pass 1: logits + max ----
  float lg[4];
  float mx = -3.0e38f;
  const float4* u4 = (const float4*)us;
  #pragma unroll
  for (int rep = 0; rep < 4; ++rep) {
    int t = tid + rep * NT2_;
    float a = -3.0e38f;
    if (t < len) {
      const float4* h4 = (const float4*)(g_H + ((size_t)b * T_ + t) * DH_);
      float s = qbk;
      #pragma unroll
      for (int j = 0; j < 24; ++j) {
        float4 hh = h4[j]; float4 uu = u4[j];
        s += hh.x * uu.x + hh.y * uu.y + hh.z * uu.z + hh.w * uu.w;
      }
      a = s;
    }
    lg[rep] = a;
    mx = fmaxf(mx, a);
  }
  #pragma unroll
  for (int o = 16; o; o >>= 1) mx = fmaxf(mx, __shfl_xor_sync(~0u, mx, o));
  if ((tid & 31) == 0) red[tid >> 5] = mx;
  __syncthreads();
  if (tid == 0) sc[1] = fmaxf(fmaxf(red[0], red[1]), fmaxf(red[2], red[3]));
  __syncthreads();
  const float gmax = sc[1];

  // ---- softmax numerators + denom ----
  float psum = 0.f;
  #pragma unroll
  for (int rep = 0; rep < 4; ++rep) {
    int t = tid + rep * NT2_;
    float e = (t < len) ? __expf(lg[rep] - gmax) : 0.f;
    alpha[t] = e;
    psum += e;
  }
  #pragma unroll
  for (int o = 16; o; o >>= 1) psum += __shfl_xor_sync(~0u, psum, o);
  if ((tid & 31) == 0) red[tid >> 5] = psum;
  __syncthreads();
  if (tid == 0) sc[2] = 1.f / (red[0] + red[1] + red[2] + red[3]);
  __syncthreads();
  const float inv = sc[2];

  // ---- write alpha output ----
  float* outA = out + B_ + (size_t)b * T_;
  #pragma unroll
  for (int rep = 0; rep < 4; ++rep) {
    int t = tid + rep * NT2_;
    outA[t] = alpha[t] * inv;
  }

  // ---- pass 2: s = sum_t alpha_t * H_t ----
  if (tid < DH_) {
    float s = 0.f;
    const float* hp = g_H + (size_t)b * T_ * DH_ + tid;
    int t = 0;
    for (; t + 4 <= len; t += 4) {
      s += alpha[t]     * hp[(size_t)t * DH_];
      s += alpha[t + 1] * hp[(size_t)(t + 1) * DH_];
      s += alpha[t + 2] * hp[(size_t)(t + 2) * DH_];
      s += alpha[t + 3] * hp[(size_t)(t + 3) * DH_];
    }
    for (; t < len; ++t) s += alpha[t] * hp[(size_t)t * DH_];
    ss[tid] = s * inv;
  }
  __syncthreads();

  // ---- ctx + feats ----
  if (tid < DH_) {
    float a = bv[tid];
    const float* wr = Wv + tid * DH_;
    #pragma unroll 8
    for (int d = 0; d < DH_; ++d) a += ss[d] * wr[d];
    feats[tid] = a;
    feats[DH_ + tid] = hTs[tid];
  }
  __syncthreads();

  // ---- gate logits ----
  if (tid < 6) {
    float a = bg[tid];
    const float* wr = Wg + tid * 2 * DH_;
    #pragma unroll 8
    for (int f = 0; f < 2 * DH_; ++f) a += feats[f] * wr[f];
    red[tid] = a;
    out[B_ + (size_t)B_ * T_ + (size_t)b * 6 + tid] = a;
  }
  __syncthreads();

  // ---- top-2 + softmax weights ----
  if (tid == 0) {
    int i0 = 0; float v0 = red[0];
    #pragma unroll
    for (int e = 1; e < 6; ++e) if (red[e] > v0) { v0 = red[e]; i0 = e; }
    int i1 = (i0 == 0) ? 1 : 0; float v1 = red[i1];
    #pragma unroll
    for (int e = 0; e < 6; ++e) if (e != i0 && red[e] > v1) { v1 = red[e]; i1 = e; }
    float e1 = __expf(v1 - v0);
    float den = 1.f + e1;
    sc[3] = 1.f / den;   // pi0
    sc[4] = e1 / den;    // pi1
    isc[0] = i0; isc[1] = i1;
  }
  __syncthreads();

  // ---- evaluate the 2 selected experts ----
  for (int it = tid; it < 192; it += NT2_) {
    int slot = it / DH_, hd = it % DH_;
    int e = isc[slot];
    const float* wr = We1 + ((size_t)e * DH_ + hd) * (2 * DH_);
    float a = be1[e * DH_ + hd];
    #pragma unroll 8
    for (int f = 0; f < 2 * DH_; ++f) a += feats[f] * wr[f];
    a = fmaxf(a, 0.f);
    red[32 + it] = a * We2[e * DH_ + hd];
  }
  __syncthreads();
  if (tid == 0) {
    float o0 = be2[isc[0]], o1 = be2[isc[1]];
    #pragma unroll 8
    for (int j = 0; j < DH_; ++j) { o0 += red[32 + j]; o1 += red[32 + DH_ + j]; }
    out[b] = sc[3] * o0 + sc[4] * o1;
  }
}

// =====================================================================
extern "C" void kernel_launch(void* const* d_in, const int* in_sizes, int n_in,
                              void* d_out, int out_size)
{
  const float* x       = (const float*)d_in[0];
  const int*   lengths = (const int*)  d_in[1];
  // d_in[2] = mask (derived from lengths; unused)
  const float* Wih = (const float*)d_in[3];
  const float* Whh = (const float*)d_in[4];
  const float* bih = (const float*)d_in[5];
  const float* bhh = (const float*)d_in[6];
  const float* Wq  = (const float*)d_in[7];
  const float* bq  = (const float*)d_in[8];
  const float* Wk  = (const float*)d_in[9];
  const float* bk  = (const float*)d_in[10];
  const float* Wv  = (const float*)d_in[11];
  const float* bv  = (const float*)d_in[12];
  const float* Wg  = (const float*)d_in[13];
  const float* bg  = (const float*)d_in[14];
  const float* We1 = (const float*)d_in[15];
  const float* be1 = (const float*)d_in[16];
  const float* We2 = (const float*)d_in[17];
  const float* be2 = (const float*)d_in[18];
  float* out = (float*)d_out;

  cudaFuncSetAttribute(lstm_kernel, cudaFuncAttributeMaxDynamicSharedMemorySize, SMEM1);

  lstm_kernel<<<NB1_, NT1_, SMEM1>>>(x, lengths, Wih, Whh, bih, bhh);
  attn_moe_kernel<<<B_, NT2_>>>(lengths, Wq, bq, Wk, bk, Wv, bv, Wg, bg,
                                We1, be1, We2, be2, out);
}

// round 3
// speedup vs baseline: 1.0114x; 1.0114x over previous
#include <cuda_runtime.h>
#include <math.h>
#include <stdint.h>
#include <stddef.h>

// ---------------- problem constants ----------------
#define B_    2048
#define T_    512
#define DIN_  32
#define DH_   96
#define G4_   384        // 4*DH
#define KIN_  128        // DIN + DH
#define RPB_  14         // batch rows per LSTM block
#define NB1_  147        // ceil(2048/14)
#define NT1_  384        // LSTM threads/block
#define NT2_  288        // attention threads/block (9 warps)
#define PITCH 20         // floats per h-row of staging (80 B, 16B-aligned)
#define XP    16         // floats per x-row of staging (64 B)

// ---------------- device scratch (no runtime alloc allowed) ----------------
__device__ float g_H [(size_t)B_ * T_ * DH_];   // hidden states (only t < len written)
__device__ float g_hT[(size_t)B_ * DH_];        // final hidden state
__device__ int   g_steer;                        // sink for ncu-steering kernels

// ---------------- smem layout (bytes) for LSTM kernel ----------------
#define OFF_W     0
#define SZ_W      (KIN_ * G4_ * 4)              // 196608
#define OFF_H     (OFF_W + SZ_W)
#define SZ_H      (DH_ * PITCH * 4)             // 7680
#define OFF_X     (OFF_H + SZ_H)
#define SZ_X      (2 * 32 * XP * 4)             // 4096 (double-buffered x staging)
#define OFF_G2    (OFF_X + SZ_X)
#define SZ_G2     (7 * G4_ * 8)                 // 21504 (float2 per (rowpair, gatecol))
#define OFF_BIAS  (OFF_G2 + SZ_G2)
#define SZ_BIAS   (G4_ * 4)                     // 1536
#define OFF_LEN   (OFF_BIAS + SZ_BIAS)
#define SZ_LEN    (16 * 4)
#define SMEM1     (OFF_LEN + SZ_LEN)            // 231,488 B (<= 232,448 limit)

// packed f32x2 FMA (sm_103a; only reachable via PTX)
#define FMA2(acc, in, wv) \
  asm("fma.rn.f32x2 %0, %1, %2, %0;" : "+l"(acc) : "l"(in), "l"(wv))

__device__ __forceinline__ float sigf(float xv) {
  return __fdividef(1.f, 1.f + __expf(-xv));
}
__device__ __forceinline__ float tanh_acc(float xv) {
  float e = __expf(2.f * xv);            // inf-safe: +inf -> 1, 0 -> -1
  return 1.f - __fdividef(2.f, e + 1.f);
}

// one (row-pair, dim) activation update
__device__ __forceinline__ void lstm_act(
    const float2* __restrict__ G2, int rp, int d, int t,
    float bi, float bf, float bgg, float bo,
    int L0, int L1, float& cx, float& cy,
    float* hslot, float* H0, float* H1)
{
  float2 gI = G2[rp*G4_ + d];
  float2 gF = G2[rp*G4_ + 96  + d];
  float2 gG = G2[rp*G4_ + 192 + d];
  float2 gO = G2[rp*G4_ + 288 + d];
  float2 hold = *(float2*)hslot;

  { // row A (.x)
    float ii = sigf(gI.x + bi);
    float ff = sigf(gF.x + bf);
    float tg = tanh_acc(gG.x + bgg);
    float oo = sigf(gO.x + bo);
    float cn = ff * cx + ii * tg;
    float hn = oo * tanh_acc(cn);
    bool  m  = (t < L0);
    cx = m ? cn : cx;
    hold.x = m ? hn : hold.x;
    if (m) H0[(size_t)t * DH_] = hn;
  }
  { // row B (.y)
    float ii = sigf(gI.y + bi);
    float ff = sigf(gF.y + bf);
    float tg = tanh_acc(gG.y + bgg);
    float oo = sigf(gO.y + bo);
    float cn = ff * cy + ii * tg;
    float hn = oo * tanh_acc(cn);
    bool  m  = (t < L1);
    cy = m ? cn : cy;
    hold.y = m ? hn : hold.y;
    if (m) H1[(size_t)t * DH_] = hn;
  }
  *(float2*)hslot = hold;
}

// x-part GEMM: 32 k-rows, accumulates into xg[0..6]
__device__ __forceinline__ void xg_gemm(const float* __restrict__ Xb,
                                        const float* __restrict__ Wcx,
                                        unsigned long long* xg)
{
  #pragma unroll
  for (int k = 0; k < 32; ++k) {
    float wq = Wcx[k * G4_];
    unsigned long long wv;
    asm("mov.b64 %0, {%1,%1};" : "=l"(wv) : "f"(wq));
    const float* row = Xb + k * XP;
    ulonglong2 p0 = *(const ulonglong2*)(row);
    ulonglong2 p1 = *(const ulonglong2*)(row + 4);
    ulonglong2 p2 = *(const ulonglong2*)(row + 8);
    unsigned long long p6 = *(const unsigned long long*)(row + 12);
    FMA2(xg[0], p0.x, wv); FMA2(xg[1], p0.y, wv);
    FMA2(xg[2], p1.x, wv); FMA2(xg[3], p1.y, wv);
    FMA2(xg[4], p2.x, wv); FMA2(xg[5], p2.y, wv);
    FMA2(xg[6], p6,   wv);
  }
}

// =====================================================================
// Kernel 1: fused LSTM over all timesteps. One block = 14 batch rows.
// x-part GEMM overlapped with MUFU-heavy activation phase.
// =====================================================================
__global__ void __launch_bounds__(NT1_, 1)
lstm_kernel(const float* __restrict__ x, const int* __restrict__ lengths,
            const float* __restrict__ Wih, const float* __restrict__ Whh,
            const float* __restrict__ bih, const float* __restrict__ bhh)
{
  extern __shared__ char smem[];
  float* Wsm  = (float*)(smem + OFF_W);     // [k=128][j=384]; k<32 = x-rows
  float* hrow = (float*)(smem + OFF_H);     // [d=96][PITCH]; (d, r) at d*PITCH+r
  float* xrow = (float*)(smem + OFF_X);     // [2][k=32][XP]
  float* g2f  = (float*)(smem + OFF_G2);    // float2 [rp=7][j=384]
  float* bias = (float*)(smem + OFF_BIAS);  // [384]
  int*   lenm = (int*)(smem + OFF_LEN);     // [14] + maxlen at [15]

  const int tid = threadIdx.x;
  const int b0  = blockIdx.x * RPB_;

  // ---- load combined weights (k-major) ----
  for (int idx = tid; idx < G4_ * KIN_; idx += NT1_) {
    int j = idx >> 7, k = idx & 127;
    float v = (k < DIN_) ? Wih[j * DIN_ + k] : Whh[j * DH_ + (k - DIN_)];
    Wsm[k * G4_ + j] = v;
  }
  for (int j = tid; j < G4_; j += NT1_) bias[j] = bih[j] + bhh[j];
  for (int i = tid; i < DH_ * PITCH; i += NT1_) hrow[i] = 0.f;
  // stage x(0) -> buf0, x(1) -> buf1
  for (int idx = tid; idx < RPB_ * DIN_; idx += NT1_) {
    int r = idx >> 5, k = idx & 31;
    float v0 = 0.f, v1 = 0.f;
    if (b0 + r < B_) {
      const float* px = &x[(size_t)(b0 + r) * T_ * DIN_ + k];
      v0 = px[0];
      v1 = px[DIN_];
    }
    xrow[k * XP + r] = v0;
    xrow[32 * XP + k * XP + r] = v1;
  }
  if (tid < 16) {
    int L = 0;
    if (tid < RPB_ && (b0 + tid) < B_) L = lengths[b0 + tid];
    lenm[tid] = L;
  }
  __syncthreads();
  if (tid == 0) {
    int m = 0;
    #pragma unroll
    for (int r = 0; r < RPB_; ++r) m = max(m, lenm[r]);
    lenm[15] = m;
  }
  __syncthreads();
  const int maxlen = lenm[15];

  // ---- per-thread static assignments ----
  const int wrp  = tid >> 5, lane = tid & 31;
  const int e0  = wrp * 56 + lane;            // every warp owns 56 act elements
  const int rp0 = e0 / 96, d0 = e0 % 96;
  const bool has1 = (lane < 24);
  const int e1  = wrp * 56 + 32 + lane;
  const int rp1 = min(e1 / 96, 6);
  const int d1  = e1 % 96;

  float bi0 = bias[d0], bf0 = bias[96 + d0], bg0 = bias[192 + d0], bo0 = bias[288 + d0];
  float bi1 = bias[d1], bf1 = bias[96 + d1], bg1 = bias[192 + d1], bo1 = bias[288 + d1];
  const int L00 = lenm[2 * rp0], L01 = lenm[2 * rp0 + 1];
  const int L10 = lenm[2 * rp1], L11 = lenm[2 * rp1 + 1];
  float cx0 = 0.f, cy0 = 0.f, cx1 = 0.f, cy1 = 0.f;
  float* hs0 = &hrow[d0 * PITCH + 2 * rp0];
  float* hs1 = &hrow[d1 * PITCH + 2 * rp1];
  const int r00 = min(b0 + 2 * rp0,     B_ - 1);
  const int r01 = min(b0 + 2 * rp0 + 1, B_ - 1);
  const int r10 = min(b0 + 2 * rp1,     B_ - 1);
  const int r11 = min(b0 + 2 * rp1 + 1, B_ - 1);
  float* H00 = &g_H[(size_t)r00 * T_ * DH_ + d0];
  float* H01 = &g_H[(size_t)r01 * T_ * DH_ + d0];
  float* H10 = &g_H[(size_t)r10 * T_ * DH_ + d1];
  float* H11 = &g_H[(size_t)r11 * T_ * DH_ + d1];

  // x prefetch assignments (448 scalars: idx = tid, tid+384)
  const int xr0 = tid >> 5, xk0 = tid & 31;
  const float* xp0 = (b0 + xr0 < B_) ? &x[(size_t)(b0 + xr0) * T_ * DIN_ + xk0] : 0;
  const int xs0 = xk0 * XP + xr0;
  const int xi1 = tid + NT1_;
  const bool hasx1 = (xi1 < RPB_ * DIN_);
  const int xr1 = xi1 >> 5, xk1 = xi1 & 31;
  const float* xp1 = (hasx1 && (b0 + xr1) < B_) ? &x[(size_t)(b0 + xr1) * T_ * DIN_ + xk1] : 0;
  const int xs1 = hasx1 ? (xk1 * XP + xr1) : xs0;

  const float2* G2 = (const float2*)g2f;
  unsigned long long* g2u = (unsigned long long*)g2f;
  const float* Wch = Wsm + 32 * G4_ + tid;   // h-part weights (k=32..127)
  const float* Wcx = Wsm + tid;              // x-part weights (k=0..31)

  // pre-loop: xg accumulators for t=0 from x(0) (buf 0)
  unsigned long long xga[7] = {0,0,0,0,0,0,0};
  if (maxlen > 0) xg_gemm(xrow, Wcx, xga);

  for (int t = 0; t < maxlen; ++t) {
    // ------------- phase A: h-part GEMM (k = 32..127) -------------
    unsigned long long a0 = xga[0], a1 = xga[1], a2 = xga[2], a3 = xga[3],
                       a4 = xga[4], a5 = xga[5], a6 = xga[6];
    #pragma unroll 16
    for (int k = 0; k < 96; ++k) {
      float w = Wch[k * G4_];
      unsigned long long wv;
      asm("mov.b64 %0, {%1,%1};" : "=l"(wv) : "f"(w));
      const float* row = hrow + k * PITCH;
      ulonglong2 p0 = *(const ulonglong2*)(row);
      ulonglong2 p1 = *(const ulonglong2*)(row + 4);
      ulonglong2 p2 = *(const ulonglong2*)(row + 8);
      unsigned long long p6 = *(const unsigned long long*)(row + 12);
      FMA2(a0, p0.x, wv); FMA2(a1, p0.y, wv);
      FMA2(a2, p1.x, wv); FMA2(a3, p1.y, wv);
      FMA2(a4, p2.x, wv); FMA2(a5, p2.y, wv);
      FMA2(a6, p6,   wv);
    }
    g2u[0 * G4_ + tid] = a0;
    g2u[1 * G4_ + tid] = a1;
    g2u[2 * G4_ + tid] = a2;
    g2u[3 * G4_ + tid] = a3;
    g2u[4 * G4_ + tid] = a4;
    g2u[5 * G4_ + tid] = a5;
    g2u[6 * G4_ + tid] = a6;

    // prefetch x(t+2) into registers
    float xv0 = 0.f, xv1 = 0.f;
    if (t + 2 < T_) {
      if (xp0) xv0 = __ldg(xp0 + (size_t)(t + 2) * DIN_);
      if (xp1) xv1 = __ldg(xp1 + (size_t)(t + 2) * DIN_);
    }
    __syncthreads();

    // ------------- phase B: activations (MUFU) + xg GEMM for t+1 (FMA) -------------
    xga[0] = 0; xga[1] = 0; xga[2] = 0; xga[3] = 0; xga[4] = 0; xga[5] = 0; xga[6] = 0;

    lstm_act(G2, rp0, d0, t, bi0, bf0, bg0, bo0, L00, L01, cx0, cy0, hs0, H00, H01);
    if (has1)
      lstm_act(G2, rp1, d1, t, bi1, bf1, bg1, bo1, L10, L11, cx1, cy1, hs1, H10, H11);

    if (t + 1 < maxlen)
      xg_gemm(xrow + ((t + 1) & 1) * (32 * XP), Wcx, xga);

    // stage x(t+2) into the buffer not being read
    if (t + 2 < T_) {
      float* buf = xrow + (t & 1) * (32 * XP);
      buf[xs0] = xv0;
      if (hasx1) buf[xs1] = xv1;
    }
    __syncthreads();
  }

  // ---- write final hidden state ----
  for (int idx = tid; idx < RPB_ * DH_; idx += NT1_) {
    int r = idx / DH_, d = idx % DH_;
    if (b0 + r < B_)
      g_hT[(size_t)(b0 + r) * DH_ + d] = hrow[d * PITCH + r];
  }
}

// =====================================================================
// Kernel 2: attention (K/V folded into weight space, online softmax,
// single pass over H) + top-2 MoE. One block per batch row, 9 warps.
// =====================================================================
__global__ void __launch_bounds__(NT2_)
attn_moe_kernel(const int* __restrict__ lengths,
                const float* __restrict__ Wq, const float* __restrict__ bq,
                const float* __restrict__ Wk, const float* __restrict__ bk,
                const float* __restrict__ Wv, const float* __restrict__ bv,
                const float* __restrict__ Wg, const float* __restrict__ bg,
                const float* __restrict__ We1, const float* __restrict__ be1,
                const float* __restrict__ We2, const float* __restrict__ be2,
                float* __restrict__ out)
{
  __shared__ float hTs[DH_], Qs[DH_], us[DH_], ssum[DH_], feats[2 * DH_];
  __shared__ float logits[T_];
  __shared__ float wm[9], wz[9], fw[9];
  __shared__ float accs[9][DH_];
  __shared__ float red[224];
  __shared__ float sc[4];
  __shared__ int   isc[2];

  const int b = blockIdx.x;
  const int tid = threadIdx.x;
  const int lane = tid & 31;
  const int w = tid >> 5;
  const float rs = 0.10206207261596575f;   // 1/sqrt(96)

  if (tid < DH_) hTs[tid] = g_hT[(size_t)b * DH_ + tid];
  __syncthreads();

  if (tid < DH_) {
    float a = bq[tid];
    const float* wr = Wq + tid * DH_;
    #pragma unroll 8
    for (int k = 0; k < DH_; ++k) a += hTs[k] * wr[k];
    Qs[tid] = a;
  }
  __syncthreads();

  if (tid < DH_) {
    float a = 0.f;
    #pragma unroll 8
    for (int j = 0; j < DH_; ++j) a += Qs[j] * Wk[j * DH_ + tid];
    us[tid] = a * rs;
  }
  if (tid == NT2_ - 1) {
    float a = 0.f;
    for (int j = 0; j < DH_; ++j) a += Qs[j] * bk[j];
    sc[0] = a * rs;
  }
  __syncthreads();

  const int len = lengths[b];
  const float qbk = sc[0];

  // ---- single pass: online softmax + weighted-H accumulation ----
  {
    float u0 = us[lane], u1 = us[lane + 32], u2 = us[lane + 64];
    float m = -3.0e38f, z = 0.f, a0 = 0.f, a1 = 0.f, a2 = 0.f;
    const float* hb = g_H + (size_t)b * T_ * DH_;
    for (int t = w; t < len; t += 9) {
      const float* hp = hb + (size_t)t * DH_;
      float h0 = __ldg(hp + lane);
      float h1 = __ldg(hp + lane + 32);
      float h2 = __ldg(hp + lane + 64);
      float s = h0 * u0 + h1 * u1 + h2 * u2;
      #pragma unroll
      for (int o = 16; o; o >>= 1) s += __shfl_xor_sync(~0u, s, o);
      s += qbk;
      if (lane == 0) logits[t] = s;
      float mn = fmaxf(m, s);
      float corr = __expf(m - mn);
      float f = __expf(s - mn);
      m = mn;
      z  = z  * corr + f;
      a0 = a0 * corr + f * h0;
      a1 = a1 * corr + f * h1;
      a2 = a2 * corr + f * h2;
    }
    if (lane == 0) { wm[w] = m; wz[w] = z; }
    accs[w][lane]      = a0;
    accs[w][lane + 32] = a1;
    accs[w][lane + 64] = a2;
  }
  __syncthreads();

  if (tid == 0) {
    float gm = -3.0e38f;
    #pragma unroll
    for (int k = 0; k < 9; ++k) gm = fmaxf(gm, wm[k]);
    float Z = 0.f;
    #pragma unroll
    for (int k = 0; k < 9; ++k) {
      float fk = __expf(wm[k] - gm);
      fw[k] = fk;
      Z += wz[k] * fk;
    }
    sc[1] = gm;
    sc[2] = 1.f / Z;
  }
  __syncthreads();
  const float gmax = sc[1];
  const float inv  = sc[2];

  if (tid < DH_) {
    float s = 0.f;
    #pragma unroll
    for (int k = 0; k < 9; ++k) s += accs[k][tid] * fw[k];
    ssum[tid] = s * inv;
  }
  // alpha outputs
  {
    float* outA = out + B_ + (size_t)b * T_;
    for (int t = tid; t < T_; t += NT2_)
      outA[t] = (t < len) ? __expf(logits[t] - gmax) * inv : 0.f;
  }
  __syncthreads();

  // ---- ctx + feats ----
  if (tid < DH_) {
    float a = bv[tid];
    const float* wr = Wv + tid * DH_;
    #pragma unroll 8
    for (int d = 0; d < DH_; ++d) a += ssum[d] * wr[d];
    feats[tid] = a;
    feats[DH_ + tid] = hTs[tid];
  }
  __syncthreads();

  // ---- gate logits ----
  if (tid < 6) {
    float a = bg[tid];
    const float* wr = Wg + tid * 2 * DH_;
    #pragma unroll 8
    for (int f = 0; f < 2 * DH_; ++f) a += feats[f] * wr[f];
    red[tid] = a;
    out[B_ + (size_t)B_ * T_ + (size_t)b * 6 + tid] = a;
  }
  __syncthreads();

  // ---- top-2 + softmax weights ----
  if (tid == 0) {
    int i0 = 0; float v0 = red[0];
    #pragma unroll
    for (int e = 1; e < 6; ++e) if (red[e] > v0) { v0 = red[e]; i0 = e; }
    int i1 = (i0 == 0) ? 1 : 0; float v1 = red[i1];
    #pragma unroll
    for (int e = 0; e < 6; ++e) if (e != i0 && red[e] > v1) { v1 = red[e]; i1 = e; }
    float e1 = __expf(v1 - v0);
    float den = 1.f + e1;
    sc[1] = 1.f / den;   // pi0
    sc[2] = e1 / den;    // pi1
    isc[0] = i0; isc[1] = i1;
  }
  __syncthreads();

  // ---- evaluate the 2 selected experts ----
  if (tid < 192) {
    int slot = tid / DH_, hd = tid % DH_;
    int e = isc[slot];
    const float* wr = We1 + ((size_t)e * DH_ + hd) * (2 * DH_);
    float a = be1[e * DH_ + hd];
    #pragma unroll 8
    for (int f = 0; f < 2 * DH_; ++f) a += feats[f] * wr[f];
    a = fmaxf(a, 0.f);
    red[32 + tid] = a * We2[e * DH_ + hd];
  }
  __syncthreads();
  if (tid == 0) {
    float o0 = be2[isc[0]], o1 = be2[isc[1]];
    #pragma unroll 8
    for (int j = 0; j < DH_; ++j) { o0 += red[32 + j]; o1 += red[32 + DH_ + j]; }
    out[b] = sc[1] * o0 + sc[2] * o1;
  }
}

// tiny kernels to steer ncu's "-s 5 -c 1" onto lstm_kernel next round
// (launch period becomes 5: L,A,X,X,X -> launch #5 = L)
__global__ void steer_kernel(int i) {
  if (threadIdx.x == 0) g_steer = i;
}

// =====================================================================
extern "C" void kernel_launch(void* const* d_in, const int* in_sizes, int n_in,
                              void* d_out, int out_size)
{
  const float* x       = (const float*)d_in[0];
  const int*   lengths = (const int*)  d_in[1];
  // d_in[2] = mask (derived from lengths; unused)
  const float* Wih = (const float*)d_in[3];
  const float* Whh = (const float*)d_in[4];
  const float* bih = (const float*)d_in[5];
  const float* bhh = (const float*)d_in[6];
  const float* Wq  = (const float*)d_in[7];
  const float* bq  = (const float*)d_in[8];
  const float* Wk  = (const float*)d_in[9];
  const float* bk  = (const float*)d_in[10];
  const float* Wv  = (const float*)d_in[11];
  const float* bv  = (const float*)d_in[12];
  const float* Wg  = (const float*)d_in[13];
  const float* bg  = (const float*)d_in[14];
  const float* We1 = (const float*)d_in[15];
  const float* be1 = (const float*)d_in[16];
  const float* We2 = (const float*)d_in[17];
  const float* be2 = (const float*)d_in[18];
  float* out = (float*)d_out;

  cudaFuncSetAttribute(lstm_kernel, cudaFuncAttributeMaxDynamicSharedMemorySize, SMEM1);

  lstm_kernel<<<NB1_, NT1_, SMEM1>>>(x, lengths, Wih, Whh, bih, bhh);
  attn_moe_kernel<<<B_, NT2_>>>(lengths, Wq, bq, Wk, bk, Wv, bv, Wg, bg,
                                We1, be1, We2, be2, out);
  steer_kernel<<<1, 32>>>(0);
  steer_kernel<<<1, 32>>>(1);
  steer_kernel<<<1, 32>>>(2);
}

// round 4
// speedup vs baseline: 1.4659x; 1.4494x over previous
#include <cuda_runtime.h>
#include <math.h>
#include <stdint.h>
#include <stddef.h>

// ---------------- problem constants ----------------
#define B_    2048
#define T_    512
#define DIN_  32
#define DH_   96
#define G4_   384        // 4*DH
#define KIN_  128        // DIN + DH
#define GRP_  8          // batch rows per group
#define NGRP  256        // 2048 / 8
#define NB1_  147        // persistent LSTM blocks
#define NT1_  384        // LSTM threads/block
#define NT2_  288        // attention threads/block (9 warps)
#define PITCH 12         // floats per k-row of staging (48 B, 16B-aligned)

// ---------------- device scratch (no runtime alloc allowed) ----------------
__device__ float g_H [(size_t)B_ * T_ * DH_];   // hidden states (only t < len written)
__device__ float g_hT[(size_t)B_ * DH_];        // final hidden state
__device__ int   g_order[B_];                   // rows sorted by length (ascending)
__device__ int   g_next;                        // work-stealing counter

// ---------------- smem layout (bytes) for LSTM kernel ----------------
#define OFF_W     0
#define SZ_W      (KIN_ * G4_ * 4)              // 196608
#define OFF_INP   (OFF_W + SZ_W)
#define SZ_INP    (KIN_ * PITCH * 4)            // 6144
#define OFF_G2    (OFF_INP + SZ_INP)
#define SZ_G2     (4 * G4_ * 8)                 // 12288 (float2 [rp=4][j=384])
#define OFF_BIAS  (OFF_G2 + SZ_G2)
#define SZ_BIAS   (G4_ * 4)                     // 1536
#define OFF_META  (OFF_BIAS + SZ_BIAS)
#define SZ_META   (32 * 4)                      // rowid[8], len[8], maxlen, gshare
#define SMEM1     (OFF_META + SZ_META)          // 216,704 B

// packed f32x2 FMA (sm_103a; only reachable via PTX)
#define FMA2(acc, in, wv) \
  asm("fma.rn.f32x2 %0, %1, %2, %0;" : "+l"(acc) : "l"(in), "l"(wv))

__device__ __forceinline__ float sigf(float xv) {
  return __fdividef(1.f, 1.f + __expf(-xv));
}
__device__ __forceinline__ float tanh_acc(float xv) {
  float e = __expf(2.f * xv);            // inf-safe: +inf -> 1, 0 -> -1
  return 1.f - __fdividef(2.f, e + 1.f);
}

// =====================================================================
// Kernel 0: counting sort of rows by length (ascending) + counter reset
// =====================================================================
__global__ void __launch_bounds__(512)
sort_kernel(const int* __restrict__ lengths)
{
  __shared__ int hist[512];
  __shared__ int scanA[512];
  const int tid = threadIdx.x;
  hist[tid] = 0;
  __syncthreads();
  for (int r = tid; r < B_; r += 512)
    atomicAdd(&hist[lengths[r] - 1], 1);
  __syncthreads();
  int v = hist[tid];
  scanA[tid] = v;
  __syncthreads();
  for (int off = 1; off < 512; off <<= 1) {
    int cur = scanA[tid];
    int add = (tid >= off) ? scanA[tid - off] : 0;
    __syncthreads();
    scanA[tid] = cur + add;
    __syncthreads();
  }
  hist[tid] = scanA[tid] - v;   // exclusive offsets (reused as cursors)
  __syncthreads();
  for (int r = tid; r < B_; r += 512) {
    int pos = atomicAdd(&hist[lengths[r] - 1], 1);
    g_order[pos] = r;
  }
  if (tid == 0) g_next = 0;
}

// =====================================================================
// Kernel 1: persistent LSTM. 147 blocks steal 8-row groups (longest
// first). Weights stay in SMEM across groups.
// =====================================================================
__global__ void __launch_bounds__(NT1_, 1)
lstm_kernel(const float* __restrict__ x, const int* __restrict__ lengths,
            const float* __restrict__ Wih, const float* __restrict__ Whh,
            const float* __restrict__ bih, const float* __restrict__ bhh)
{
  extern __shared__ char smem[];
  float* Wsm  = (float*)(smem + OFF_W);     // [k=128][j=384]
  float* inp  = (float*)(smem + OFF_INP);   // [k=128][PITCH]; (k, r) at k*PITCH+r
  float* g2f  = (float*)(smem + OFF_G2);    // float2 [rp=4][j=384]
  float* bias = (float*)(smem + OFF_BIAS);  // [384]
  int*   meta = (int*)(smem + OFF_META);    // rowid[0..7], len[8..15], [16]=maxlen, [17]=gshare

  const int tid = threadIdx.x;

  // ---- load combined weights (k-major) once ----
  for (int idx = tid; idx < G4_ * KIN_; idx += NT1_) {
    int j = idx >> 7, k = idx & 127;
    float v = (k < DIN_) ? Wih[j * DIN_ + k] : Whh[j * DH_ + (k - DIN_)];
    Wsm[k * G4_ + j] = v;
  }
  for (int j = tid; j < G4_; j += NT1_) bias[j] = bih[j] + bhh[j];
  __syncthreads();

  // ---- static per-thread assignments ----
  const int rp0 = tid / 96, d0 = tid % 96;               // act element
  const float bi0 = bias[d0], bf0 = bias[96 + d0],
              bg0 = bias[192 + d0], bo0 = bias[288 + d0];
  float* hs0 = &inp[(32 + d0) * PITCH + 2 * rp0];
  const bool xact = (tid < GRP_ * DIN_);                  // x prefetch lane
  const int xr = tid >> 5, xk = tid & 31;
  const int xslot = xk * PITCH + xr;
  const float* Wc = Wsm + tid;
  const float2* G2 = (const float2*)g2f;
  unsigned long long* g2u = (unsigned long long*)g2f;

  for (;;) {
    // ---- grab next group (longest-first) ----
    if (tid == 0) {
      int g = atomicAdd(&g_next, 1);
      meta[17] = (g < NGRP) ? (NGRP - 1 - g) : -1;
    }
    __syncthreads();
    const int gi = meta[17];
    if (gi < 0) break;

    if (tid < GRP_) {
      int row = g_order[gi * GRP_ + tid];
      meta[tid] = row;
      meta[8 + tid] = lengths[row];
    }
    // zero staging (x slots overwritten below; h slots must be 0)
    for (int i = tid; i < KIN_ * PITCH; i += NT1_) inp[i] = 0.f;
    __syncthreads();
    if (tid == 0) {
      int m = 0;
      #pragma unroll
      for (int r = 0; r < GRP_; ++r) m = max(m, meta[8 + r]);
      meta[16] = m;
    }
    __syncthreads();
    const int maxlen = meta[16];

    // per-group per-thread state
    const int L0 = meta[8 + 2 * rp0], L1 = meta[8 + 2 * rp0 + 1];
    const int r0 = meta[2 * rp0], r1 = meta[2 * rp0 + 1];
    float* H0 = &g_H[(size_t)r0 * T_ * DH_ + d0];
    float* H1 = &g_H[(size_t)r1 * T_ * DH_ + d0];
    float cx = 0.f, cy = 0.f;
    const float* xbase = xact ? &x[(size_t)meta[xr] * T_ * DIN_ + xk] : 0;

    // stage x(0)
    if (xact) inp[xslot] = __ldg(xbase);
    __syncthreads();

    for (int t = 0; t < maxlen; ++t) {
      // ---- GEMM: g[rp][j=tid] over 128 k ----
      unsigned long long a0 = 0, a1 = 0, a2 = 0, a3 = 0;
      #pragma unroll 16
      for (int k = 0; k < KIN_; ++k) {
        float w = Wc[k * G4_];
        unsigned long long wv;
        asm("mov.b64 %0, {%1,%1};" : "=l"(wv) : "f"(w));
        const float* row = inp + k * PITCH;
        ulonglong2 p0 = *(const ulonglong2*)(row);
        ulonglong2 p1 = *(const ulonglong2*)(row + 4);
        FMA2(a0, p0.x, wv); FMA2(a1, p0.y, wv);
        FMA2(a2, p1.x, wv); FMA2(a3, p1.y, wv);
      }
      g2u[0 * G4_ + tid] = a0;
      g2u[1 * G4_ + tid] = a1;
      g2u[2 * G4_ + tid] = a2;
      g2u[3 * G4_ + tid] = a3;

      // prefetch x(t+1)
      float xv = 0.f;
      if (xact && (t + 1 < T_)) xv = __ldg(xbase + (size_t)(t + 1) * DIN_);
      __syncthreads();

      // ---- activations + state update ----
      {
        float2 gI = G2[rp0 * G4_ + d0];
        float2 gF = G2[rp0 * G4_ + 96  + d0];
        float2 gG = G2[rp0 * G4_ + 192 + d0];
        float2 gO = G2[rp0 * G4_ + 288 + d0];
        float2 hold = *(float2*)hs0;
        { // row A
          float ii = sigf(gI.x + bi0);
          float ff = sigf(gF.x + bf0);
          float tg = tanh_acc(gG.x + bg0);
          float oo = sigf(gO.x + bo0);
          float cn = ff * cx + ii * tg;
          float hn = oo * tanh_acc(cn);
          bool  m  = (t < L0);
          cx = m ? cn : cx;
          hold.x = m ? hn : hold.x;
          if (m) H0[(size_t)t * DH_] = hn;
        }
        { // row B
          float ii = sigf(gI.y + bi0);
          float ff = sigf(gF.y + bf0);
          float tg = tanh_acc(gG.y + bg0);
          float oo = sigf(gO.y + bo0);
          float cn = ff * cy + ii * tg;
          float hn = oo * tanh_acc(cn);
          bool  m  = (t < L1);
          cy = m ? cn : cy;
          hold.y = m ? hn : hold.y;
          if (m) H1[(size_t)t * DH_] = hn;
        }
        *(float2*)hs0 = hold;
      }

      if (xact && (t + 1 < T_)) inp[xslot] = xv;
      __syncthreads();
    }

    // ---- write final hidden state for this group ----
    #pragma unroll
    for (int rep = 0; rep < 2; ++rep) {
      int idx = tid + rep * NT1_;
      int r = idx / DH_, d = idx % DH_;
      g_hT[(size_t)meta[r] * DH_ + d] = inp[(32 + d) * PITCH + r];
    }
    // loop-top barrier (after atomic) separates these reads/writes from
    // the next group's meta/staging updates
  }
}

// =====================================================================
// Kernel 2: attention (K/V folded into weight space, online softmax,
// single pass over H) + top-2 MoE. One block per batch row, 9 warps.
// =====================================================================
__global__ void __launch_bounds__(NT2_)
attn_moe_kernel(const int* __restrict__ lengths,
                const float* __restrict__ Wq, const float* __restrict__ bq,
                const float* __restrict__ Wk, const float* __restrict__ bk,
                const float* __restrict__ Wv, const float* __restrict__ bv,
                const float* __restrict__ Wg, const float* __restrict__ bg,
                const float* __restrict__ We1, const float* __restrict__ be1,
                const float* __restrict__ We2, const float* __restrict__ be2,
                float* __restrict__ out)
{
  __shared__ float hTs[DH_], Qs[DH_], us[DH_], ssum[DH_], feats[2 * DH_];
  __shared__ float logits[T_];
  __shared__ float wm[9], wz[9], fw[9];
  __shared__ float accs[9][DH_];
  __shared__ float red[224];
  __shared__ float sc[4];
  __shared__ int   isc[2];

  const int b = blockIdx.x;
  const int tid = threadIdx.x;
  const int lane = tid & 31;
  const int w = tid >> 5;
  const float rs = 0.10206207261596575f;   // 1/sqrt(96)

  if (tid < DH_) hTs[tid] = g_hT[(size_t)b * DH_ + tid];
  __syncthreads();

  if (tid < DH_) {
    float a = bq[tid];
    const float* wr = Wq + tid * DH_;
    #pragma unroll 8
    for (int k = 0; k < DH_; ++k) a += hTs[k] * wr[k];
    Qs[tid] = a;
  }
  __syncthreads();

  if (tid < DH_) {
    float a = 0.f;
    #pragma unroll 8
    for (int j = 0; j < DH_; ++j) a += Qs[j] * Wk[j * DH_ + tid];
    us[tid] = a * rs;
  }
  if (tid == NT2_ - 1) {
    float a = 0.f;
    for (int j = 0; j < DH_; ++j) a += Qs[j] * bk[j];
    sc[0] = a * rs;
  }
  __syncthreads();

  const int len = lengths[b];
  const float qbk = sc[0];

  // ---- single pass: online softmax + weighted-H accumulation ----
  {
    float u0 = us[lane], u1 = us[lane + 32], u2 = us[lane + 64];
    float m = -3.0e38f, z = 0.f, a0 = 0.f, a1 = 0.f, a2 = 0.f;
    const float* hb = g_H + (size_t)b * T_ * DH_;
    for (int t = w; t < len; t += 9) {
      const float* hp = hb + (size_t)t * DH_;
      float h0 = __ldg(hp + lane);
      float h1 = __ldg(hp + lane + 32);
      float h2 = __ldg(hp + lane + 64);
      float s = h0 * u0 + h1 * u1 + h2 * u2;
      #pragma unroll
      for (int o = 16; o; o >>= 1) s += __shfl_xor_sync(~0u, s, o);
      s += qbk;
      if (lane == 0) logits[t] = s;
      float mn = fmaxf(m, s);
      float corr = __expf(m - mn);
      float f = __expf(s - mn);
      m = mn;
      z  = z  * corr + f;
      a0 = a0 * corr + f * h0;
      a1 = a1 * corr + f * h1;
      a2 = a2 * corr + f * h2;
    }
    if (lane == 0) { wm[w] = m; wz[w] = z; }
    accs[w][lane]      = a0;
    accs[w][lane + 32] = a1;
    accs[w][lane + 64] = a2;
  }
  __syncthreads();

  if (tid == 0) {
    float gm = -3.0e38f;
    #pragma unroll
    for (int k = 0; k < 9; ++k) gm = fmaxf(gm, wm[k]);
    float Z = 0.f;
    #pragma unroll
    for (int k = 0; k < 9; ++k) {
      float fk = __expf(wm[k] - gm);
      fw[k] = fk;
      Z += wz[k] * fk;
    }
    sc[1] = gm;
    sc[2] = 1.f / Z;
  }
  __syncthreads();
  const float gmax = sc[1];
  const float inv  = sc[2];

  if (tid < DH_) {
    float s = 0.f;
    #pragma unroll
    for (int k = 0; k < 9; ++k) s += accs[k][tid] * fw[k];
    ssum[tid] = s * inv;
  }
  // alpha outputs
  {
    float* outA = out + B_ + (size_t)b * T_;
    for (int t = tid; t < T_; t += NT2_)
      outA[t] = (t < len) ? __expf(logits[t] - gmax) * inv : 0.f;
  }
  __syncthreads();

  // ---- ctx + feats ----
  if (tid < DH_) {
    float a = bv[tid];
    const float* wr = Wv + tid * DH_;
    #pragma unroll 8
    for (int d = 0; d < DH_; ++d) a += ssum[d] * wr[d];
    feats[tid] = a;
    feats[DH_ + tid] = hTs[tid];
  }
  __syncthreads();

  // ---- gate logits ----
  if (tid < 6) {
    float a = bg[tid];
    const float* wr = Wg + tid * 2 * DH_;
    #pragma unroll 8
    for (int f = 0; f < 2 * DH_; ++f) a += feats[f] * wr[f];
    red[tid] = a;
    out[B_ + (size_t)B_ * T_ + (size_t)b * 6 + tid] = a;
  }
  __syncthreads();

  // ---- top-2 + softmax weights ----
  if (tid == 0) {
    int i0 = 0; float v0 = red[0];
    #pragma unroll
    for (int e = 1; e < 6; ++e) if (red[e] > v0) { v0 = red[e]; i0 = e; }
    int i1 = (i0 == 0) ? 1 : 0; float v1 = red[i1];
    #pragma unroll
    for (int e = 0; e < 6; ++e) if (e != i0 && red[e] > v1) { v1 = red[e]; i1 = e; }
    float e1 = __expf(v1 - v0);
    float den = 1.f + e1;
    sc[1] = 1.f / den;   // pi0
    sc[2] = e1 / den;    // pi1
    isc[0] = i0; isc[1] = i1;
  }
  __syncthreads();

  // ---- evaluate the 2 selected experts ----
  if (tid < 192) {
    int slot = tid / DH_, hd = tid % DH_;
    int e = isc[slot];
    const float* wr = We1 + ((size_t)e * DH_ + hd) * (2 * DH_);
    float a = be1[e * DH_ + hd];
    #pragma unroll 8
    for (int f = 0; f < 2 * DH_; ++f) a += feats[f] * wr[f];
    a = fmaxf(a, 0.f);
    red[32 + tid] = a * We2[e * DH_ + hd];
  }
  __syncthreads();
  if (tid == 0) {
    float o0 = be2[isc[0]], o1 = be2[isc[1]];
    #pragma unroll 8
    for (int j = 0; j < DH_; ++j) { o0 += red[32 + j]; o1 += red[32 + DH_ + j]; }
    out[b] = sc[1] * o0 + sc[2] * o1;
  }
}

// =====================================================================
extern "C" void kernel_launch(void* const* d_in, const int* in_sizes, int n_in,
                              void* d_out, int out_size)
{
  const float* x       = (const float*)d_in[0];
  const int*   lengths = (const int*)  d_in[1];
  // d_in[2] = mask (derived from lengths; unused)
  const float* Wih = (const float*)d_in[3];
  const float* Whh = (const float*)d_in[4];
  const float* bih = (const float*)d_in[5];
  const float* bhh = (const float*)d_in[6];
  const float* Wq  = (const float*)d_in[7];
  const float* bq  = (const float*)d_in[8];
  const float* Wk  = (const float*)d_in[9];
  const float* bk  = (const float*)d_in[10];
  const float* Wv  = (const float*)d_in[11];
  const float* bv  = (const float*)d_in[12];
  const float* Wg  = (const float*)d_in[13];
  const float* bg  = (const float*)d_in[14];
  const float* We1 = (const float*)d_in[15];
  const float* be1 = (const float*)d_in[16];
  const float* We2 = (const float*)d_in[17];
  const float* be2 = (const float*)d_in[18];
  float* out = (float*)d_out;

  cudaFuncSetAttribute(lstm_kernel, cudaFuncAttributeMaxDynamicSharedMemorySize, SMEM1);

  sort_kernel<<<1, 512>>>(lengths);
  lstm_kernel<<<NB1_, NT1_, SMEM1>>>(x, lengths, Wih, Whh, bih, bhh);
  attn_moe_kernel<<<B_, NT2_>>>(lengths, Wq, bq, Wk, bk, Wv, bv, Wg, bg,
                                We1, be1, We2, be2, out);
}